// round 16
// baseline (speedup 1.0000x reference)
#include <cuda_runtime.h>
#include <cuda_bf16.h>
#include <cstdint>

#define DD 128
#define MAXN 50176            // >= N, multiple of 256 (= 196*256)
#define MAXE (1 << 20)
#define NBLK 196              // scan blocks
#define FILLB 120             // fill blocks appended to scan launch

// ---------------- scratch (static __device__; allocation-free) ----------------
__device__ __align__(128) int   g_cnt[MAXN];        // drained back to 0 by fill each run
__device__ __align__(128) int   g_off[MAXN + 1];
__device__ __align__(128) int   g_blk_state[NBLK];  // zeroed by init each run
__device__            int   g_scan_done;            // zeroed by init each run
__device__ __align__(128) int   g_csr[MAXE];
__device__ __align__(128) float g_conv [MAXN * DD];
__device__ __align__(128) float g_m    [MAXN * DD];
__device__ __align__(128) float g_std  [MAXN * DD];
// bf16 split half-operand buffers, ROW-MAJOR [rows x 128] each (disjoint per input!)
__device__ __align__(128) __nv_bfloat16 g_Hhi[MAXN * 128], g_Hlo[MAXN * 128];   // split(h)
__device__ __align__(128) __nv_bfloat16 g_Chi[MAXN * 128], g_Clo[MAXN * 128];   // split(ctx)
__device__ __align__(128) __nv_bfloat16 g_Nhi[MAXN * 128], g_Nlo[MAXN * 128];   // split(neigh_mean)
__device__ __align__(128) __nv_bfloat16 g_Shi[MAXN * 128], g_Slo[MAXN * 128];   // split(std)
__device__ __align__(128) __nv_bfloat16 g_Vhi[MAXN * 128], g_Vlo[MAXN * 128];   // split(conv_agg)
__device__ __align__(128) __nv_bfloat16 g_Bhi[3][128 * 256];
__device__ __align__(128) __nv_bfloat16 g_Blo[3][128 * 256];

// ---------------- helpers ----------------
__device__ __forceinline__ void split_bf16(float f, __nv_bfloat16& h, __nv_bfloat16& l) {
    h = __float2bfloat16(f);
    l = __float2bfloat16(f - __bfloat162float(h));
}
__device__ __forceinline__ void mma_bf16(float* d, const uint32_t* a, uint32_t b0, uint32_t b1) {
    asm volatile("mma.sync.aligned.m16n8k16.row.col.f32.bf16.bf16.f32 "
                 "{%0,%1,%2,%3}, {%4,%5,%6,%7}, {%8,%9}, {%0,%1,%2,%3};"
                 : "+f"(d[0]), "+f"(d[1]), "+f"(d[2]), "+f"(d[3])
                 : "r"(a[0]), "r"(a[1]), "r"(a[2]), "r"(a[3]), "r"(b0), "r"(b1));
}
__device__ __forceinline__ uint32_t smem_u32(const void* p) {
    uint32_t a;
    asm("{ .reg .u64 t; cvta.to.shared.u64 t, %1; cvt.u32.u64 %0, t; }" : "=r"(a) : "l"(p));
    return a;
}
__device__ __forceinline__ void cp_async16(uint32_t dst, const void* src) {
    asm volatile("cp.async.ca.shared.global [%0], [%1], 16;" :: "r"(dst), "l"(src));
}
__device__ __forceinline__ void cp_commit() { asm volatile("cp.async.commit_group;" ::: "memory"); }
template<int W> __device__ __forceinline__ void cp_wait() {
    asm volatile("cp.async.wait_group %0;" :: "n"(W) : "memory");
}
__device__ __forceinline__ void ldsm_x4(uint32_t* r, uint32_t addr) {
    asm volatile("ldmatrix.sync.aligned.m8n8.x4.shared.b16 {%0,%1,%2,%3}, [%4];"
                 : "=r"(r[0]), "=r"(r[1]), "=r"(r[2]), "=r"(r[3]) : "r"(addr));
}
__device__ __forceinline__ void write_split4(__nv_bfloat16* Hh, __nv_bfloat16* Hl,
                                             size_t off, float4 s) {
    __nv_bfloat16 a, b;
    __nv_bfloat162 hh0, hh1, ll0, ll1;
    split_bf16(s.x, a, b); hh0.x = a; ll0.x = b;
    split_bf16(s.y, a, b); hh0.y = a; ll0.y = b;
    split_bf16(s.z, a, b); hh1.x = a; ll1.x = b;
    split_bf16(s.w, a, b); hh1.y = a; ll1.y = b;
    *(__nv_bfloat162*)&Hh[off] = hh0; *(__nv_bfloat162*)&Hh[off + 2] = hh1;
    *(__nv_bfloat162*)&Hl[off] = ll0; *(__nv_bfloat162*)&Hl[off + 2] = ll1;
}

// ===== init: convW3 + zero scan state + split(h)/split(ctx) + edge count =====
__global__ void init_k(const float* __restrict__ Wm, const float* __restrict__ W_self,
                       const float* __restrict__ W_neigh, const float* __restrict__ Wg,
                       const float* __restrict__ h, const float* __restrict__ ctx,
                       const int* __restrict__ dst,
                       int E, int N, int rowsTot)
{
    int i = blockIdx.x * blockDim.x + threadIdx.x;
    if (i < 3 * 32768) {
        int g = i >> 15;
        int r = i & 32767;
        int n = r >> 8, k = r & 255;
        float w;
        if (g == 0)      w = Wm[k * 128 + n];
        else if (g == 1) w = (k < 128) ? W_self[k * 128 + n] : W_neigh[(k - 128) * 128 + n];
        else             w = Wg[k * 128 + n];
        __nv_bfloat16 hh, ll; split_bf16(w, hh, ll);
        g_Bhi[g][n * 256 + k] = hh;
        g_Blo[g][n * 256 + k] = ll;
        return;
    }
    i -= 3 * 32768;
    if (i < NBLK + 1) {
        if (i < NBLK) g_blk_state[i] = 0; else g_scan_done = 0;
        return;
    }
    i -= NBLK + 1;
    if (i < rowsTot * 128) {
        int r = i >> 7;
        int cp = (i & 127) * 2;                 // 0..254
        int isCtx = cp >= 128;
        int c = cp & 127;
        float2 v = make_float2(0.f, 0.f);
        if (r < N) {
            const float* S = isCtx ? ctx : h;
            v = *(const float2*)&S[(size_t)r * 128 + c];
        }
        __nv_bfloat16 h0, l0, h1, l1;
        split_bf16(v.x, h0, l0);
        split_bf16(v.y, h1, l1);
        size_t off = (size_t)r * 128 + c;
        __nv_bfloat162 hh; hh.x = h0; hh.y = h1;
        __nv_bfloat162 ll; ll.x = l0; ll.y = l1;
        if (isCtx) { *(__nv_bfloat162*)&g_Chi[off] = hh; *(__nv_bfloat162*)&g_Clo[off] = ll; }
        else       { *(__nv_bfloat162*)&g_Hhi[off] = hh; *(__nv_bfloat162*)&g_Hlo[off] = ll; }
        return;
    }
    i -= rowsTot * 128;
    if (i < E) {
        int d = dst[i];
        d = min(max(d, 0), N - 1);
        atomicAdd(&g_cnt[d], 1);   // g_cnt all-zero at entry (drained by fill each run)
    }
}

// ===== scan (decoupled-lookback) + fill in ONE launch =====
__global__ void scan_fill_k(const int* __restrict__ src, const int* __restrict__ dst,
                            int E, int N) {
    __shared__ int sm[256];
    __shared__ int s_prefix;
    int t = threadIdx.x, lane = t & 31;
    if ((int)blockIdx.x >= NBLK) {
        if (t == 0) {
            while (atomicAdd(&g_scan_done, 0) < NBLK) { }
        }
        __syncthreads();
        __threadfence();
        int fb = blockIdx.x - NBLK;
        for (int i = fb * 256 + t; i < E; i += FILLB * 256) {
            int d = dst[i];
            d = min(max(d, 0), N - 1);
            int pos = g_off[d] + (atomicSub(&g_cnt[d], 1) - 1);  // drains g_cnt to 0
            if (pos >= 0 && pos < MAXE) {
                int s = src[i];
                g_csr[pos] = min(max(s, 0), N - 1);
            }
        }
        return;
    }
    int b = blockIdx.x;
    int v = g_cnt[b * 256 + t];
    sm[t] = v;
    __syncthreads();
    int acc = v;
    #pragma unroll
    for (int o = 1; o < 256; o <<= 1) {
        int p = (t >= o) ? sm[t - o] : 0;
        __syncthreads();
        acc += p; sm[t] = acc;
        __syncthreads();
    }
    int total = sm[255];
    if (t == 0) atomicExch(&g_blk_state[b], (total << 1) | 1);
    if (t < 32) {
        int prefix = 0;
        for (int base = 0; base < b; base += 32) {
            int idx = base + lane;
            int st = 0;
            if (idx < b) {
                do { st = atomicAdd(&g_blk_state[idx], 0); } while ((st & 1) == 0);
            }
            int c = (idx < b) ? (st >> 1) : 0;
            #pragma unroll
            for (int o = 16; o; o >>= 1) c += __shfl_xor_sync(0xffffffffu, c, o);
            prefix += c;
        }
        if (lane == 0) s_prefix = prefix;
    }
    __syncthreads();
    g_off[b * 256 + t] = s_prefix + acc - v;
    if (b == NBLK - 1 && t == 255) g_off[MAXN] = s_prefix + acc;
    __threadfence();
    __syncthreads();
    if (t == 0) atomicAdd(&g_scan_done, 1);
}

// ===== agg gather body (warp per dst, unroll x4) =====
__device__ __forceinline__ float4 gather_mean(const float* __restrict__ S, int d, int lane) {
    int e0 = g_off[d], e1 = g_off[d + 1];
    float4 s = make_float4(0.f, 0.f, 0.f, 0.f);
    int e = e0;
    for (; e + 3 < e1; e += 4) {
        int i0 = g_csr[e], i1 = g_csr[e + 1], i2 = g_csr[e + 2], i3 = g_csr[e + 3];
        float4 v0 = *(const float4*)&S[(size_t)i0 * 128 + lane * 4];
        float4 v1 = *(const float4*)&S[(size_t)i1 * 128 + lane * 4];
        float4 v2 = *(const float4*)&S[(size_t)i2 * 128 + lane * 4];
        float4 v3 = *(const float4*)&S[(size_t)i3 * 128 + lane * 4];
        s.x += (v0.x + v1.x) + (v2.x + v3.x);
        s.y += (v0.y + v1.y) + (v2.y + v3.y);
        s.z += (v0.z + v1.z) + (v2.z + v3.z);
        s.w += (v0.w + v1.w) + (v2.w + v3.w);
    }
    for (; e < e1; e++) {
        int i0 = g_csr[e];
        float4 v0 = *(const float4*)&S[(size_t)i0 * 128 + lane * 4];
        s.x += v0.x; s.y += v0.y; s.z += v0.z; s.w += v0.w;
    }
    float iv = 1.0f / fmaxf((float)(e1 - e0), 1.0f);
    s.x *= iv; s.y *= iv; s.z *= iv; s.w *= iv;
    return s;
}

// ================= HMMA GEMM (2-stage cp.async + ldmatrix) + interleaved agg role ======
// A operand comes from two DISJOINT half buffers [rows x 128]: low (k 0..127), high (k 128..255).
#define SPAD 40
#define SROWB (SPAD * 2)
#define O_AH 0
#define O_AL 10240
#define O_BH 20480
#define O_BL 30720
#define STAGE_BYTES 40960
#define CPAD 132
#define SM_TOTAL (2 * STAGE_BYTES)

// MODE 0: GEMM: g_m = relu(LN(D+bias)); agg role: gather(h) -> N buffers
// MODE 1: GEMM: g_std = D+bias, split -> S buffers; agg role: gather(g_m) -> V buffers + g_conv
// MODE 2: GEMM only: out = sig(D+bias)*g_std + (1-sig)*g_conv
template<int MODE>
__global__ __launch_bounds__(256, 2)
void mma_k(const __nv_bfloat16* __restrict__ AhiL, const __nv_bfloat16* __restrict__ AloL,
           const __nv_bfloat16* __restrict__ AhiH, const __nv_bfloat16* __restrict__ AloH,
           const __nv_bfloat16* __restrict__ Bhi, const __nv_bfloat16* __restrict__ Blo,
           const float* __restrict__ bias,
           const float* __restrict__ ln_g, const float* __restrict__ ln_b,
           float* __restrict__ O0,
           __nv_bfloat16* __restrict__ Ssplit_hi, __nv_bfloat16* __restrict__ Ssplit_lo,
           const float* __restrict__ std_in, const float* __restrict__ conv_in,
           const float* __restrict__ gsrc,                   // agg gather source (h or g_m)
           __nv_bfloat16* __restrict__ AggBh, __nv_bfloat16* __restrict__ AggBl,
           float* __restrict__ agg_f32,                      // MODE1: g_conv out
           int N, int rowsTot)
{
    int tid = threadIdx.x;
    int tiles = rowsTot >> 7;
    int G = gridDim.x;
    int b = blockIdx.x;
    long prev = (long)b * tiles / G;
    long nxt  = (long)(b + 1) * tiles / G;
    int lane = tid & 31, wid = tid >> 5;

    if (MODE != 2 && nxt == prev) {
        // ---- agg role (warp per dst node, grid-strided); disjoint buffers from GEMM role ----
        int aggIdx = b - (int)prev;
        int aggBlocks = G - tiles;
        int w0 = aggIdx * 8 + wid;
        int wstep = aggBlocks * 8;
        for (int d = w0; d < rowsTot; d += wstep) {
            float4 s = gather_mean(gsrc, d, lane);
            if (MODE == 1)
                *(float4*)&agg_f32[(size_t)d * 128 + lane * 4] = s;
            write_split4(AggBh, AggBl, (size_t)d * 128 + lane * 4, s);
        }
        return;
    }
    int tile = (int)prev;

    extern __shared__ __align__(16) char smem[];
    uint32_t sb = smem_u32(smem);
    int wm = wid & 3, wn = wid >> 2;

    float acc[2][8][4];
    #pragma unroll
    for (int mt = 0; mt < 2; mt++)
        #pragma unroll
        for (int nt = 0; nt < 8; nt++)
            #pragma unroll
            for (int q = 0; q < 4; q++) acc[mt][nt][q] = 0.f;

    int cr0 = tid >> 2, cc0 = (tid & 3) * 16;
    int cr1 = (tid + 256) >> 2, cc1 = ((tid + 256) & 3) * 16;

    auto load_chunk = [&](int ch) {
        uint32_t base = sb + (uint32_t)(ch & 1) * STAGE_BYTES;
        const __nv_bfloat16* Ah = (ch < 4) ? AhiL : AhiH;
        const __nv_bfloat16* Al = (ch < 4) ? AloL : AloH;
        int chh = ch & 3;
        size_t a0 = ((size_t)tile * 128 + cr0) * 128 + chh * 32;
        size_t a1 = ((size_t)tile * 128 + cr1) * 128 + chh * 32;
        size_t b0 = (size_t)cr0 * 256 + ch * 32;
        size_t b1 = (size_t)cr1 * 256 + ch * 32;
        uint32_t s0 = base + cr0 * SROWB;
        uint32_t s1 = base + cr1 * SROWB;
        cp_async16(s0 + O_AH + cc0, (const char*)Ah + a0 * 2 + cc0);
        cp_async16(s1 + O_AH + cc1, (const char*)Ah + a1 * 2 + cc1);
        cp_async16(s0 + O_AL + cc0, (const char*)Al + a0 * 2 + cc0);
        cp_async16(s1 + O_AL + cc1, (const char*)Al + a1 * 2 + cc1);
        cp_async16(s0 + O_BH + cc0, (const char*)Bhi + b0 * 2 + cc0);
        cp_async16(s1 + O_BH + cc1, (const char*)Bhi + b1 * 2 + cc1);
        cp_async16(s0 + O_BL + cc0, (const char*)Blo + b0 * 2 + cc0);
        cp_async16(s1 + O_BL + cc1, (const char*)Blo + b1 * 2 + cc1);
        cp_commit();
    };

    load_chunk(0);
    for (int ch = 0; ch < 8; ch++) {
        if (ch < 7) { load_chunk(ch + 1); cp_wait<1>(); }
        else        { cp_wait<0>(); }
        __syncthreads();
        uint32_t base = sb + (uint32_t)(ch & 1) * STAGE_BYTES;

        int arow = wm * 32 + (lane & 7) + (lane & 8);
        int acolh = ((lane >> 4) << 3);
        int brow_base = wn * 64 + ((lane >> 4) << 3) + (lane & 7);
        int bcol_sel = (((lane >> 3) & 1) << 3);

        #pragma unroll
        for (int kk = 0; kk < 32; kk += 16) {
            uint32_t ah[2][4], al[2][4];
            #pragma unroll
            for (int mt = 0; mt < 2; mt++) {
                uint32_t ao = (uint32_t)(arow + mt * 16) * SROWB + (uint32_t)(kk + acolh) * 2;
                ldsm_x4(ah[mt], base + O_AH + ao);
                ldsm_x4(al[mt], base + O_AL + ao);
            }
            #pragma unroll
            for (int p = 0; p < 4; p++) {
                uint32_t bo = (uint32_t)(brow_base + p * 16) * SROWB + (uint32_t)(kk + bcol_sel) * 2;
                uint32_t bh[4], bl[4];
                ldsm_x4(bh, base + O_BH + bo);
                ldsm_x4(bl, base + O_BL + bo);
                #pragma unroll
                for (int sub = 0; sub < 2; sub++) {
                    int nt = p * 2 + sub;
                    #pragma unroll
                    for (int mt = 0; mt < 2; mt++) {
                        mma_bf16(acc[mt][nt], ah[mt], bh[sub * 2], bh[sub * 2 + 1]);
                        mma_bf16(acc[mt][nt], al[mt], bh[sub * 2], bh[sub * 2 + 1]);
                        mma_bf16(acc[mt][nt], ah[mt], bl[sub * 2], bl[sub * 2 + 1]);
                    }
                }
            }
        }
        __syncthreads();
    }

    // ---- stage C to smem ----
    int gid = lane >> 2, qid = lane & 3;
    float* Cs = (float*)smem;
    #pragma unroll
    for (int mt = 0; mt < 2; mt++) {
        #pragma unroll
        for (int nt = 0; nt < 8; nt++) {
            int r0 = wm * 32 + mt * 16 + gid;
            int c0 = wn * 64 + nt * 8 + qid * 2;
            Cs[(r0    ) * CPAD + c0    ] = acc[mt][nt][0];
            Cs[(r0    ) * CPAD + c0 + 1] = acc[mt][nt][1];
            Cs[(r0 + 8) * CPAD + c0    ] = acc[mt][nt][2];
            Cs[(r0 + 8) * CPAD + c0 + 1] = acc[mt][nt][3];
        }
    }
    __syncthreads();

    for (int rr = wid * 16; rr < wid * 16 + 16; rr++) {
        int row = tile * 128 + rr;
        int c = lane * 4;
        if (row >= N) continue;   // padded rows: outputs discarded; S buffers stay zero
        float4 v = *(const float4*)&Cs[rr * CPAD + c];
        float4 bv = *(const float4*)&bias[c];
        v.x += bv.x; v.y += bv.y; v.z += bv.z; v.w += bv.w;

        if (MODE == 0) {
            float s = v.x + v.y + v.z + v.w;
            float sq = v.x * v.x + v.y * v.y + v.z * v.z + v.w * v.w;
            #pragma unroll
            for (int o = 16; o; o >>= 1) {
                s  += __shfl_xor_sync(0xffffffffu, s,  o);
                sq += __shfl_xor_sync(0xffffffffu, sq, o);
            }
            float mu = s * (1.f / 128.f);
            float var = sq * (1.f / 128.f) - mu * mu;
            float r = rsqrtf(var + 1e-5f);
            float4 gv = *(const float4*)&ln_g[c];
            float4 lb = *(const float4*)&ln_b[c];
            float4 o;
            o.x = fmaxf((v.x - mu) * r * gv.x + lb.x, 0.f);
            o.y = fmaxf((v.y - mu) * r * gv.y + lb.y, 0.f);
            o.z = fmaxf((v.z - mu) * r * gv.z + lb.z, 0.f);
            o.w = fmaxf((v.w - mu) * r * gv.w + lb.w, 0.f);
            *(float4*)&O0[(size_t)row * 128 + c] = o;
        } else if (MODE == 1) {
            *(float4*)&O0[(size_t)row * 128 + c] = v;
            write_split4(Ssplit_hi, Ssplit_lo, (size_t)row * 128 + c, v);
        } else {
            float4 sv = *(const float4*)&std_in[(size_t)row * 128 + c];
            float4 cv = *(const float4*)&conv_in[(size_t)row * 128 + c];
            float4 o; float g;
            g = 1.f / (1.f + expf(-v.x)); o.x = g * sv.x + (1.f - g) * cv.x;
            g = 1.f / (1.f + expf(-v.y)); o.y = g * sv.y + (1.f - g) * cv.y;
            g = 1.f / (1.f + expf(-v.z)); o.z = g * sv.z + (1.f - g) * cv.z;
            g = 1.f / (1.f + expf(-v.w)); o.w = g * sv.w + (1.f - g) * cv.w;
            *(float4*)&O0[(size_t)row * 128 + c] = o;
        }
    }
}

// ================= launch =================
extern "C" void kernel_launch(void* const* d_in, const int* in_sizes, int n_in,
                              void* d_out, int out_size)
{
    const float* h      = (const float*)d_in[0];
    const float* ctx    = (const float*)d_in[1];
    const int*   src    = (const int*)  d_in[2];
    const int*   dst    = (const int*)  d_in[3];
    const float* W_self = (const float*)d_in[4];
    const float* W_neigh= (const float*)d_in[5];
    const float* b_sage = (const float*)d_in[6];
    const float* Wm     = (const float*)d_in[7];
    const float* bm     = (const float*)d_in[8];
    const float* ln_g   = (const float*)d_in[9];
    const float* ln_b   = (const float*)d_in[10];
    const float* Wg     = (const float*)d_in[11];
    const float* bg     = (const float*)d_in[12];
    float* out = (float*)d_out;

    int N = in_sizes[0] / 128;
    if (N < 1) N = 1;
    if (N > MAXN) N = MAXN;
    int E = in_sizes[2];
    int tiles = (N + 127) / 128;
    int rowsTot = tiles * 128;

    // resolve device addresses of __device__ symbols (GB300/ATS pitfall)
    float *p_conv, *p_m, *p_std;
    __nv_bfloat16 *pHh, *pHl, *pCh, *pCl, *pNh, *pNl, *pSh, *pSl, *pVh, *pVl, *pBh, *pBl;
    cudaGetSymbolAddress((void**)&p_conv, g_conv);
    cudaGetSymbolAddress((void**)&p_m,    g_m);
    cudaGetSymbolAddress((void**)&p_std,  g_std);
    cudaGetSymbolAddress((void**)&pHh,    g_Hhi);
    cudaGetSymbolAddress((void**)&pHl,    g_Hlo);
    cudaGetSymbolAddress((void**)&pCh,    g_Chi);
    cudaGetSymbolAddress((void**)&pCl,    g_Clo);
    cudaGetSymbolAddress((void**)&pNh,    g_Nhi);
    cudaGetSymbolAddress((void**)&pNl,    g_Nlo);
    cudaGetSymbolAddress((void**)&pSh,    g_Shi);
    cudaGetSymbolAddress((void**)&pSl,    g_Slo);
    cudaGetSymbolAddress((void**)&pVh,    g_Vhi);
    cudaGetSymbolAddress((void**)&pVl,    g_Vlo);
    cudaGetSymbolAddress((void**)&pBh,    g_Bhi);
    cudaGetSymbolAddress((void**)&pBl,    g_Blo);

    cudaFuncSetAttribute(mma_k<0>, cudaFuncAttributeMaxDynamicSharedMemorySize, SM_TOTAL);
    cudaFuncSetAttribute(mma_k<1>, cudaFuncAttributeMaxDynamicSharedMemorySize, SM_TOTAL);
    cudaFuncSetAttribute(mma_k<2>, cudaFuncAttributeMaxDynamicSharedMemorySize, SM_TOTAL);

    int AGGB = 2 * tiles;   // agg blocks interleaved with GEMM blocks

    // 1) fused init: convW3 + zero scan state + split(h)/split(ctx) + count
    int init_threads = 3 * 32768 + (NBLK + 1) + rowsTot * 128 + E;
    init_k<<<(init_threads + 255) / 256, 256>>>(Wm, W_self, W_neigh, Wg, h, ctx, dst,
                                                E, N, rowsTot);
    // 2) scan + fill in one launch
    scan_fill_k<<<NBLK + FILLB, 256>>>(src, dst, E, N);
    // 3) GEMM0 [H|C]@B0 (+LN/ReLU -> g_m)  ∥  agg_h(h) -> N buffers   (disjoint)
    mma_k<0><<<tiles + AGGB, 256, SM_TOTAL>>>(pHh, pHl, pCh, pCl,
                                              pBh + 0 * 32768, pBl + 0 * 32768,
                                              bm, ln_g, ln_b, p_m, nullptr, nullptr,
                                              nullptr, nullptr,
                                              h, pNh, pNl, nullptr, N, rowsTot);
    // 4) GEMM1 [H|N]@B1 (-> g_std + S buffers)  ∥  agg_m(g_m) -> V buffers + g_conv  (disjoint)
    mma_k<1><<<tiles + AGGB, 256, SM_TOTAL>>>(pHh, pHl, pNh, pNl,
                                              pBh + 1 * 32768, pBl + 1 * 32768,
                                              b_sage, nullptr, nullptr, p_std, pSh, pSl,
                                              nullptr, nullptr,
                                              p_m, pVh, pVl, p_conv, N, rowsTot);
    // 5) GEMM2 [S|V]@B2 + fused sigmoid/blend -> out
    mma_k<2><<<tiles, 256, SM_TOTAL>>>(pSh, pSl, pVh, pVl,
                                       pBh + 2 * 32768, pBl + 2 * 32768, bg,
                                       nullptr, nullptr, out, nullptr, nullptr, p_std, p_conv,
                                       nullptr, nullptr, nullptr, nullptr, N, rowsTot);
}

// round 17
// speedup vs baseline: 1.0930x; 1.0930x over previous
#include <cuda_runtime.h>
#include <cuda_bf16.h>
#include <cstdint>

#define DD 128
#define MAXN 50176            // >= N, multiple of 256 (= 196*256)
#define MAXE (1 << 20)
#define NBLK 196              // scan blocks
#define FILLB 120             // fill blocks appended to scan launch

// ---------------- scratch (static __device__; allocation-free) ----------------
__device__ __align__(128) int   g_cnt[MAXN];        // drained back to 0 by fill each run
__device__ __align__(128) int   g_off[MAXN + 1];
__device__ __align__(128) int   g_blk_state[NBLK];  // zeroed by init each run
__device__            int   g_scan_done;            // zeroed by init each run
__device__ __align__(128) int   g_csr[MAXE];
__device__ __align__(128) float g_conv [MAXN * DD];
__device__ __align__(128) float g_m    [MAXN * DD];
__device__ __align__(128) float g_std  [MAXN * DD];
// bf16 split half-operand buffers, ROW-MAJOR [rows x 128] each (disjoint per input)
__device__ __align__(128) __nv_bfloat16 g_Hhi[MAXN * 128], g_Hlo[MAXN * 128];   // split(h)
__device__ __align__(128) __nv_bfloat16 g_Chi[MAXN * 128], g_Clo[MAXN * 128];   // split(ctx)
__device__ __align__(128) __nv_bfloat16 g_Nhi[MAXN * 128], g_Nlo[MAXN * 128];   // split(neigh_mean)
__device__ __align__(128) __nv_bfloat16 g_Shi[MAXN * 128], g_Slo[MAXN * 128];   // split(std)
__device__ __align__(128) __nv_bfloat16 g_Vhi[MAXN * 128], g_Vlo[MAXN * 128];   // split(conv_agg)
__device__ __align__(128) __nv_bfloat16 g_Bhi[3][128 * 256];
__device__ __align__(128) __nv_bfloat16 g_Blo[3][128 * 256];

// ---------------- helpers ----------------
__device__ __forceinline__ void split_bf16(float f, __nv_bfloat16& h, __nv_bfloat16& l) {
    h = __float2bfloat16(f);
    l = __float2bfloat16(f - __bfloat162float(h));
}
__device__ __forceinline__ void mma_bf16(float* d, const uint32_t* a, uint32_t b0, uint32_t b1) {
    asm volatile("mma.sync.aligned.m16n8k16.row.col.f32.bf16.bf16.f32 "
                 "{%0,%1,%2,%3}, {%4,%5,%6,%7}, {%8,%9}, {%0,%1,%2,%3};"
                 : "+f"(d[0]), "+f"(d[1]), "+f"(d[2]), "+f"(d[3])
                 : "r"(a[0]), "r"(a[1]), "r"(a[2]), "r"(a[3]), "r"(b0), "r"(b1));
}
__device__ __forceinline__ uint32_t smem_u32(const void* p) {
    uint32_t a;
    asm("{ .reg .u64 t; cvta.to.shared.u64 t, %1; cvt.u32.u64 %0, t; }" : "=r"(a) : "l"(p));
    return a;
}
__device__ __forceinline__ void cp_async16(uint32_t dst, const void* src) {
    asm volatile("cp.async.ca.shared.global [%0], [%1], 16;" :: "r"(dst), "l"(src));
}
__device__ __forceinline__ void cp_commit() { asm volatile("cp.async.commit_group;" ::: "memory"); }
template<int W> __device__ __forceinline__ void cp_wait() {
    asm volatile("cp.async.wait_group %0;" :: "n"(W) : "memory");
}
__device__ __forceinline__ void ldsm_x4(uint32_t* r, uint32_t addr) {
    asm volatile("ldmatrix.sync.aligned.m8n8.x4.shared.b16 {%0,%1,%2,%3}, [%4];"
                 : "=r"(r[0]), "=r"(r[1]), "=r"(r[2]), "=r"(r[3]) : "r"(addr));
}
__device__ __forceinline__ void write_split4(__nv_bfloat16* Hh, __nv_bfloat16* Hl,
                                             size_t off, float4 s) {
    __nv_bfloat16 a, b;
    __nv_bfloat162 hh0, hh1, ll0, ll1;
    split_bf16(s.x, a, b); hh0.x = a; ll0.x = b;
    split_bf16(s.y, a, b); hh0.y = a; ll0.y = b;
    split_bf16(s.z, a, b); hh1.x = a; ll1.x = b;
    split_bf16(s.w, a, b); hh1.y = a; ll1.y = b;
    *(__nv_bfloat162*)&Hh[off] = hh0; *(__nv_bfloat162*)&Hh[off + 2] = hh1;
    *(__nv_bfloat162*)&Hl[off] = ll0; *(__nv_bfloat162*)&Hl[off + 2] = ll1;
}

// ===== init: convW3 + zero scan state + split(h)/split(ctx) + edge count =====
__global__ void init_k(const float* __restrict__ Wm, const float* __restrict__ W_self,
                       const float* __restrict__ W_neigh, const float* __restrict__ Wg,
                       const float* __restrict__ h, const float* __restrict__ ctx,
                       const int* __restrict__ dst,
                       int E, int N, int rowsTot)
{
    int i = blockIdx.x * blockDim.x + threadIdx.x;
    if (i < 3 * 32768) {
        int g = i >> 15;
        int r = i & 32767;
        int n = r >> 8, k = r & 255;
        float w;
        if (g == 0)      w = Wm[k * 128 + n];
        else if (g == 1) w = (k < 128) ? W_self[k * 128 + n] : W_neigh[(k - 128) * 128 + n];
        else             w = Wg[k * 128 + n];
        __nv_bfloat16 hh, ll; split_bf16(w, hh, ll);
        g_Bhi[g][n * 256 + k] = hh;
        g_Blo[g][n * 256 + k] = ll;
        return;
    }
    i -= 3 * 32768;
    if (i < NBLK + 1) {
        if (i < NBLK) g_blk_state[i] = 0; else g_scan_done = 0;
        return;
    }
    i -= NBLK + 1;
    if (i < rowsTot * 128) {
        int r = i >> 7;
        int cp = (i & 127) * 2;                 // 0..254
        int isCtx = cp >= 128;
        int c = cp & 127;
        float2 v = make_float2(0.f, 0.f);
        if (r < N) {
            const float* S = isCtx ? ctx : h;
            v = *(const float2*)&S[(size_t)r * 128 + c];
        }
        __nv_bfloat16 h0, l0, h1, l1;
        split_bf16(v.x, h0, l0);
        split_bf16(v.y, h1, l1);
        size_t off = (size_t)r * 128 + c;
        __nv_bfloat162 hh; hh.x = h0; hh.y = h1;
        __nv_bfloat162 ll; ll.x = l0; ll.y = l1;
        if (isCtx) { *(__nv_bfloat162*)&g_Chi[off] = hh; *(__nv_bfloat162*)&g_Clo[off] = ll; }
        else       { *(__nv_bfloat162*)&g_Hhi[off] = hh; *(__nv_bfloat162*)&g_Hlo[off] = ll; }
        return;
    }
    i -= rowsTot * 128;
    if (i < E) {
        int d = dst[i];
        d = min(max(d, 0), N - 1);
        atomicAdd(&g_cnt[d], 1);   // g_cnt all-zero at entry (drained by fill each run)
    }
}

// ===== scan (decoupled-lookback) + fill in ONE launch =====
__global__ void scan_fill_k(const int* __restrict__ src, const int* __restrict__ dst,
                            int E, int N) {
    __shared__ int sm[256];
    __shared__ int s_prefix;
    int t = threadIdx.x, lane = t & 31;
    if ((int)blockIdx.x >= NBLK) {
        if (t == 0) {
            while (atomicAdd(&g_scan_done, 0) < NBLK) { }
        }
        __syncthreads();
        __threadfence();
        int fb = blockIdx.x - NBLK;
        for (int i = fb * 256 + t; i < E; i += FILLB * 256) {
            int d = dst[i];
            d = min(max(d, 0), N - 1);
            int pos = g_off[d] + (atomicSub(&g_cnt[d], 1) - 1);  // drains g_cnt to 0
            if (pos >= 0 && pos < MAXE) {
                int s = src[i];
                g_csr[pos] = min(max(s, 0), N - 1);
            }
        }
        return;
    }
    int b = blockIdx.x;
    int v = g_cnt[b * 256 + t];
    sm[t] = v;
    __syncthreads();
    int acc = v;
    #pragma unroll
    for (int o = 1; o < 256; o <<= 1) {
        int p = (t >= o) ? sm[t - o] : 0;
        __syncthreads();
        acc += p; sm[t] = acc;
        __syncthreads();
    }
    int total = sm[255];
    if (t == 0) atomicExch(&g_blk_state[b], (total << 1) | 1);
    if (t < 32) {
        int prefix = 0;
        for (int base = 0; base < b; base += 32) {
            int idx = base + lane;
            int st = 0;
            if (idx < b) {
                do { st = atomicAdd(&g_blk_state[idx], 0); } while ((st & 1) == 0);
            }
            int c = (idx < b) ? (st >> 1) : 0;
            #pragma unroll
            for (int o = 16; o; o >>= 1) c += __shfl_xor_sync(0xffffffffu, c, o);
            prefix += c;
        }
        if (lane == 0) s_prefix = prefix;
    }
    __syncthreads();
    g_off[b * 256 + t] = s_prefix + acc - v;
    if (b == NBLK - 1 && t == 255) g_off[MAXN] = s_prefix + acc;
    __threadfence();
    __syncthreads();
    if (t == 0) atomicAdd(&g_scan_done, 1);
}

// ===== agg gather body (warp per dst, unroll x4) =====
__device__ __forceinline__ float4 gather_mean(const float* __restrict__ S, int d, int lane) {
    int e0 = g_off[d], e1 = g_off[d + 1];
    float4 s = make_float4(0.f, 0.f, 0.f, 0.f);
    int e = e0;
    for (; e + 3 < e1; e += 4) {
        int i0 = g_csr[e], i1 = g_csr[e + 1], i2 = g_csr[e + 2], i3 = g_csr[e + 3];
        float4 v0 = *(const float4*)&S[(size_t)i0 * 128 + lane * 4];
        float4 v1 = *(const float4*)&S[(size_t)i1 * 128 + lane * 4];
        float4 v2 = *(const float4*)&S[(size_t)i2 * 128 + lane * 4];
        float4 v3 = *(const float4*)&S[(size_t)i3 * 128 + lane * 4];
        s.x += (v0.x + v1.x) + (v2.x + v3.x);
        s.y += (v0.y + v1.y) + (v2.y + v3.y);
        s.z += (v0.z + v1.z) + (v2.z + v3.z);
        s.w += (v0.w + v1.w) + (v2.w + v3.w);
    }
    for (; e < e1; e++) {
        int i0 = g_csr[e];
        float4 v0 = *(const float4*)&S[(size_t)i0 * 128 + lane * 4];
        s.x += v0.x; s.y += v0.y; s.z += v0.z; s.w += v0.w;
    }
    float iv = 1.0f / fmaxf((float)(e1 - e0), 1.0f);
    s.x *= iv; s.y *= iv; s.z *= iv; s.w *= iv;
    return s;
}

// ===== standalone agg kernels (high occupancy; run on the side stream) =====
__global__ void agg_h_k(const float* __restrict__ h,
                        __nv_bfloat16* __restrict__ Nh, __nv_bfloat16* __restrict__ Nl,
                        int rowsTot) {
    int d = (blockIdx.x * blockDim.x + threadIdx.x) >> 5;
    int lane = threadIdx.x & 31;
    if (d >= rowsTot) return;
    float4 s = gather_mean(h, d, lane);
    write_split4(Nh, Nl, (size_t)d * 128 + lane * 4, s);
}
__global__ void agg_m_k(const float* __restrict__ m,
                        __nv_bfloat16* __restrict__ Vh, __nv_bfloat16* __restrict__ Vl,
                        float* __restrict__ conv_out, int rowsTot) {
    int d = (blockIdx.x * blockDim.x + threadIdx.x) >> 5;
    int lane = threadIdx.x & 31;
    if (d >= rowsTot) return;
    float4 s = gather_mean(m, d, lane);
    *(float4*)&conv_out[(size_t)d * 128 + lane * 4] = s;
    write_split4(Vh, Vl, (size_t)d * 128 + lane * 4, s);
}

// ================= HMMA GEMM (2-stage cp.async + ldmatrix) ==================
#define SPAD 40
#define SROWB (SPAD * 2)
#define O_AH 0
#define O_AL 10240
#define O_BH 20480
#define O_BL 30720
#define STAGE_BYTES 40960
#define CPAD 132
#define SM_TOTAL (2 * STAGE_BYTES)

// MODE 0: g_m = relu(LN(D+bias))
// MODE 1: g_std = D+bias, split -> S buffers
// MODE 2: out = sig(D+bias)*g_std + (1-sig)*g_conv
template<int MODE>
__global__ __launch_bounds__(256, 2)
void mma_k(const __nv_bfloat16* __restrict__ AhiL, const __nv_bfloat16* __restrict__ AloL,
           const __nv_bfloat16* __restrict__ AhiH, const __nv_bfloat16* __restrict__ AloH,
           const __nv_bfloat16* __restrict__ Bhi, const __nv_bfloat16* __restrict__ Blo,
           const float* __restrict__ bias,
           const float* __restrict__ ln_g, const float* __restrict__ ln_b,
           float* __restrict__ O0,
           __nv_bfloat16* __restrict__ Ssplit_hi, __nv_bfloat16* __restrict__ Ssplit_lo,
           const float* __restrict__ std_in, const float* __restrict__ conv_in,
           int N, int rowsTot)
{
    int tid = threadIdx.x;
    int lane = tid & 31, wid = tid >> 5;
    int tile = blockIdx.x;

    extern __shared__ __align__(16) char smem[];
    uint32_t sb = smem_u32(smem);
    int wm = wid & 3, wn = wid >> 2;

    float acc[2][8][4];
    #pragma unroll
    for (int mt = 0; mt < 2; mt++)
        #pragma unroll
        for (int nt = 0; nt < 8; nt++)
            #pragma unroll
            for (int q = 0; q < 4; q++) acc[mt][nt][q] = 0.f;

    int cr0 = tid >> 2, cc0 = (tid & 3) * 16;
    int cr1 = (tid + 256) >> 2, cc1 = ((tid + 256) & 3) * 16;

    auto load_chunk = [&](int ch) {
        uint32_t base = sb + (uint32_t)(ch & 1) * STAGE_BYTES;
        const __nv_bfloat16* Ah = (ch < 4) ? AhiL : AhiH;
        const __nv_bfloat16* Al = (ch < 4) ? AloL : AloH;
        int chh = ch & 3;
        size_t a0 = ((size_t)tile * 128 + cr0) * 128 + chh * 32;
        size_t a1 = ((size_t)tile * 128 + cr1) * 128 + chh * 32;
        size_t b0 = (size_t)cr0 * 256 + ch * 32;
        size_t b1 = (size_t)cr1 * 256 + ch * 32;
        uint32_t s0 = base + cr0 * SROWB;
        uint32_t s1 = base + cr1 * SROWB;
        cp_async16(s0 + O_AH + cc0, (const char*)Ah + a0 * 2 + cc0);
        cp_async16(s1 + O_AH + cc1, (const char*)Ah + a1 * 2 + cc1);
        cp_async16(s0 + O_AL + cc0, (const char*)Al + a0 * 2 + cc0);
        cp_async16(s1 + O_AL + cc1, (const char*)Al + a1 * 2 + cc1);
        cp_async16(s0 + O_BH + cc0, (const char*)Bhi + b0 * 2 + cc0);
        cp_async16(s1 + O_BH + cc1, (const char*)Bhi + b1 * 2 + cc1);
        cp_async16(s0 + O_BL + cc0, (const char*)Blo + b0 * 2 + cc0);
        cp_async16(s1 + O_BL + cc1, (const char*)Blo + b1 * 2 + cc1);
        cp_commit();
    };

    load_chunk(0);
    for (int ch = 0; ch < 8; ch++) {
        if (ch < 7) { load_chunk(ch + 1); cp_wait<1>(); }
        else        { cp_wait<0>(); }
        __syncthreads();
        uint32_t base = sb + (uint32_t)(ch & 1) * STAGE_BYTES;

        int arow = wm * 32 + (lane & 7) + (lane & 8);
        int acolh = ((lane >> 4) << 3);
        int brow_base = wn * 64 + ((lane >> 4) << 3) + (lane & 7);
        int bcol_sel = (((lane >> 3) & 1) << 3);

        #pragma unroll
        for (int kk = 0; kk < 32; kk += 16) {
            uint32_t ah[2][4], al[2][4];
            #pragma unroll
            for (int mt = 0; mt < 2; mt++) {
                uint32_t ao = (uint32_t)(arow + mt * 16) * SROWB + (uint32_t)(kk + acolh) * 2;
                ldsm_x4(ah[mt], base + O_AH + ao);
                ldsm_x4(al[mt], base + O_AL + ao);
            }
            #pragma unroll
            for (int p = 0; p < 4; p++) {
                uint32_t bo = (uint32_t)(brow_base + p * 16) * SROWB + (uint32_t)(kk + bcol_sel) * 2;
                uint32_t bh[4], bl[4];
                ldsm_x4(bh, base + O_BH + bo);
                ldsm_x4(bl, base + O_BL + bo);
                #pragma unroll
                for (int sub = 0; sub < 2; sub++) {
                    int nt = p * 2 + sub;
                    #pragma unroll
                    for (int mt = 0; mt < 2; mt++) {
                        mma_bf16(acc[mt][nt], ah[mt], bh[sub * 2], bh[sub * 2 + 1]);
                        mma_bf16(acc[mt][nt], al[mt], bh[sub * 2], bh[sub * 2 + 1]);
                        mma_bf16(acc[mt][nt], ah[mt], bl[sub * 2], bl[sub * 2 + 1]);
                    }
                }
            }
        }
        __syncthreads();
    }

    // ---- stage C to smem ----
    int gid = lane >> 2, qid = lane & 3;
    float* Cs = (float*)smem;
    #pragma unroll
    for (int mt = 0; mt < 2; mt++) {
        #pragma unroll
        for (int nt = 0; nt < 8; nt++) {
            int r0 = wm * 32 + mt * 16 + gid;
            int c0 = wn * 64 + nt * 8 + qid * 2;
            Cs[(r0    ) * CPAD + c0    ] = acc[mt][nt][0];
            Cs[(r0    ) * CPAD + c0 + 1] = acc[mt][nt][1];
            Cs[(r0 + 8) * CPAD + c0    ] = acc[mt][nt][2];
            Cs[(r0 + 8) * CPAD + c0 + 1] = acc[mt][nt][3];
        }
    }
    __syncthreads();

    for (int rr = wid * 16; rr < wid * 16 + 16; rr++) {
        int row = tile * 128 + rr;
        int c = lane * 4;
        if (row >= N) continue;   // padded rows discarded; S/V buffers stay zero (static init)
        float4 v = *(const float4*)&Cs[rr * CPAD + c];
        float4 bv = *(const float4*)&bias[c];
        v.x += bv.x; v.y += bv.y; v.z += bv.z; v.w += bv.w;

        if (MODE == 0) {
            float s = v.x + v.y + v.z + v.w;
            float sq = v.x * v.x + v.y * v.y + v.z * v.z + v.w * v.w;
            #pragma unroll
            for (int o = 16; o; o >>= 1) {
                s  += __shfl_xor_sync(0xffffffffu, s,  o);
                sq += __shfl_xor_sync(0xffffffffu, sq, o);
            }
            float mu = s * (1.f / 128.f);
            float var = sq * (1.f / 128.f) - mu * mu;
            float r = rsqrtf(var + 1e-5f);
            float4 gv = *(const float4*)&ln_g[c];
            float4 lb = *(const float4*)&ln_b[c];
            float4 o;
            o.x = fmaxf((v.x - mu) * r * gv.x + lb.x, 0.f);
            o.y = fmaxf((v.y - mu) * r * gv.y + lb.y, 0.f);
            o.z = fmaxf((v.z - mu) * r * gv.z + lb.z, 0.f);
            o.w = fmaxf((v.w - mu) * r * gv.w + lb.w, 0.f);
            *(float4*)&O0[(size_t)row * 128 + c] = o;
        } else if (MODE == 1) {
            *(float4*)&O0[(size_t)row * 128 + c] = v;
            write_split4(Ssplit_hi, Ssplit_lo, (size_t)row * 128 + c, v);
        } else {
            float4 sv = *(const float4*)&std_in[(size_t)row * 128 + c];
            float4 cv = *(const float4*)&conv_in[(size_t)row * 128 + c];
            float4 o; float g;
            g = 1.f / (1.f + expf(-v.x)); o.x = g * sv.x + (1.f - g) * cv.x;
            g = 1.f / (1.f + expf(-v.y)); o.y = g * sv.y + (1.f - g) * cv.y;
            g = 1.f / (1.f + expf(-v.z)); o.z = g * sv.z + (1.f - g) * cv.z;
            g = 1.f / (1.f + expf(-v.w)); o.w = g * sv.w + (1.f - g) * cv.w;
            *(float4*)&O0[(size_t)row * 128 + c] = o;
        }
    }
}

// ================= launch (graph-branch parallelism via side stream) =================
extern "C" void kernel_launch(void* const* d_in, const int* in_sizes, int n_in,
                              void* d_out, int out_size)
{
    const float* h      = (const float*)d_in[0];
    const float* ctx    = (const float*)d_in[1];
    const int*   src    = (const int*)  d_in[2];
    const int*   dst    = (const int*)  d_in[3];
    const float* W_self = (const float*)d_in[4];
    const float* W_neigh= (const float*)d_in[5];
    const float* b_sage = (const float*)d_in[6];
    const float* Wm     = (const float*)d_in[7];
    const float* bm     = (const float*)d_in[8];
    const float* ln_g   = (const float*)d_in[9];
    const float* ln_b   = (const float*)d_in[10];
    const float* Wg     = (const float*)d_in[11];
    const float* bg     = (const float*)d_in[12];
    float* out = (float*)d_out;

    int N = in_sizes[0] / 128;
    if (N < 1) N = 1;
    if (N > MAXN) N = MAXN;
    int E = in_sizes[2];
    int tiles = (N + 127) / 128;
    int rowsTot = tiles * 128;

    // resolve device addresses of __device__ symbols (GB300/ATS pitfall)
    float *p_conv, *p_m, *p_std;
    __nv_bfloat16 *pHh, *pHl, *pCh, *pCl, *pNh, *pNl, *pSh, *pSl, *pVh, *pVl, *pBh, *pBl;
    cudaGetSymbolAddress((void**)&p_conv, g_conv);
    cudaGetSymbolAddress((void**)&p_m,    g_m);
    cudaGetSymbolAddress((void**)&p_std,  g_std);
    cudaGetSymbolAddress((void**)&pHh,    g_Hhi);
    cudaGetSymbolAddress((void**)&pHl,    g_Hlo);
    cudaGetSymbolAddress((void**)&pCh,    g_Chi);
    cudaGetSymbolAddress((void**)&pCl,    g_Clo);
    cudaGetSymbolAddress((void**)&pNh,    g_Nhi);
    cudaGetSymbolAddress((void**)&pNl,    g_Nlo);
    cudaGetSymbolAddress((void**)&pSh,    g_Shi);
    cudaGetSymbolAddress((void**)&pSl,    g_Slo);
    cudaGetSymbolAddress((void**)&pVh,    g_Vhi);
    cudaGetSymbolAddress((void**)&pVl,    g_Vlo);
    cudaGetSymbolAddress((void**)&pBh,    g_Bhi);
    cudaGetSymbolAddress((void**)&pBl,    g_Blo);

    static bool s_init = false;
    static cudaStream_t s2;
    static cudaEvent_t evI, evM0, evAH, evAM;
    if (!s_init) {
        cudaStreamCreateWithFlags(&s2, cudaStreamNonBlocking);
        cudaEventCreateWithFlags(&evI,  cudaEventDisableTiming);
        cudaEventCreateWithFlags(&evM0, cudaEventDisableTiming);
        cudaEventCreateWithFlags(&evAH, cudaEventDisableTiming);
        cudaEventCreateWithFlags(&evAM, cudaEventDisableTiming);
        cudaFuncSetAttribute(mma_k<0>, cudaFuncAttributeMaxDynamicSharedMemorySize, SM_TOTAL);
        cudaFuncSetAttribute(mma_k<1>, cudaFuncAttributeMaxDynamicSharedMemorySize, SM_TOTAL);
        cudaFuncSetAttribute(mma_k<2>, cudaFuncAttributeMaxDynamicSharedMemorySize, SM_TOTAL);
        s_init = true;
    }

    int aggBlocks = (rowsTot * 32 + 255) / 256;

    // stream0: init
    int init_threads = 3 * 32768 + (NBLK + 1) + rowsTot * 128 + E;
    init_k<<<(init_threads + 255) / 256, 256>>>(Wm, W_self, W_neigh, Wg, h, ctx, dst,
                                                E, N, rowsTot);
    cudaEventRecord(evI, 0);

    // stream0: GEMM0 [H|C]@B0 (+LN/ReLU -> g_m)
    mma_k<0><<<tiles, 256, SM_TOTAL>>>(pHh, pHl, pCh, pCl,
                                       pBh + 0 * 32768, pBl + 0 * 32768,
                                       bm, ln_g, ln_b, p_m, nullptr, nullptr,
                                       nullptr, nullptr, N, rowsTot);
    cudaEventRecord(evM0, 0);

    // side stream: CSR build + agg_h (parallel with GEMM0), then agg_m (after GEMM0)
    cudaStreamWaitEvent(s2, evI, 0);
    scan_fill_k<<<NBLK + FILLB, 256, 0, s2>>>(src, dst, E, N);
    agg_h_k<<<aggBlocks, 256, 0, s2>>>(h, pNh, pNl, rowsTot);
    cudaEventRecord(evAH, s2);
    cudaStreamWaitEvent(s2, evM0, 0);
    agg_m_k<<<aggBlocks, 256, 0, s2>>>(p_m, pVh, pVl, p_conv, rowsTot);
    cudaEventRecord(evAM, s2);

    // stream0: GEMM1 [H|N]@B1 (-> g_std + S splits) after agg_h
    cudaStreamWaitEvent(0, evAH, 0);
    mma_k<1><<<tiles, 256, SM_TOTAL>>>(pHh, pHl, pNh, pNl,
                                       pBh + 1 * 32768, pBl + 1 * 32768,
                                       b_sage, nullptr, nullptr, p_std, pSh, pSl,
                                       nullptr, nullptr, N, rowsTot);
    // stream0: GEMM2 [S|V]@B2 + sigmoid/blend -> out, after agg_m
    cudaStreamWaitEvent(0, evAM, 0);
    mma_k<2><<<tiles, 256, SM_TOTAL>>>(pSh, pSl, pVh, pVl,
                                       pBh + 2 * 32768, pBl + 2 * 32768, bg,
                                       nullptr, nullptr, out, nullptr, nullptr, p_std, p_conv,
                                       N, rowsTot);
}